// round 16
// baseline (speedup 1.0000x reference)
#include <cuda_runtime.h>
#include <cuda_fp16.h>
#include <cstdint>

#define B_   32
#define C_   128
#define N_   1024   // L*L
#define H_   8
#define DK_  64
#define HD_  512    // H*DK
#define R3_  1536   // 3*HD
#define FULL 0xffffffffu

#define QSC  0.1803368801111354f    // 0.125 * log2(e)
#define INVL 0.44721359549995793f   // 1/sqrt(5)
#define ONESH 0x3C003C00u           // f16x2 (1.0, 1.0)

// Scratch (allocation-free contract: __device__ globals), fp16
__device__ __half g_xb [(size_t)B_ * C_ * N_];
__device__ __half g_wb [(size_t)R3_ * C_];
__device__ __half g_w0b[(size_t)C_ * HD_];
__device__ __half g_qkv[(size_t)B_ * N_ * R3_];  // [b][n][r]; Q pre-scaled by QSC
__device__ __half g_att[(size_t)B_ * N_ * HD_];

__device__ __forceinline__ uint32_t smem_u32(const void* p) {
    return (uint32_t)__cvta_generic_to_shared(p);
}
// pack two f32 into f16x2: lo -> bits[15:0], hi -> bits[31:16]
__device__ __forceinline__ uint32_t pack_f16(float lo, float hi) {
    uint32_t r;
    asm("cvt.rn.f16x2.f32 %0, %1, %2;" : "=r"(r) : "f"(hi), "f"(lo));
    return r;
}
__device__ __forceinline__ uint32_t ex2_f16x2(uint32_t x) {
    uint32_t y;
    asm("ex2.approx.f16x2 %0, %1;" : "=r"(y) : "r"(x));
    return y;
}
__device__ __forceinline__ void ldsm4(uint32_t& r0, uint32_t& r1, uint32_t& r2, uint32_t& r3, uint32_t a) {
    asm volatile("ldmatrix.sync.aligned.m8n8.x4.shared.b16 {%0,%1,%2,%3},[%4];"
                 : "=r"(r0), "=r"(r1), "=r"(r2), "=r"(r3) : "r"(a));
}
__device__ __forceinline__ void ldsm4t(uint32_t& r0, uint32_t& r1, uint32_t& r2, uint32_t& r3, uint32_t a) {
    asm volatile("ldmatrix.sync.aligned.m8n8.x4.trans.shared.b16 {%0,%1,%2,%3},[%4];"
                 : "=r"(r0), "=r"(r1), "=r"(r2), "=r"(r3) : "r"(a));
}
// f16 inputs, f32 accumulator (PV, l, qkv, out)
__device__ __forceinline__ void mma_f32acc(float* d, const uint32_t* a, uint32_t b0, uint32_t b1) {
    asm volatile("mma.sync.aligned.m16n8k16.row.col.f32.f16.f16.f32 "
                 "{%0,%1,%2,%3},{%4,%5,%6,%7},{%8,%9},{%0,%1,%2,%3};"
                 : "+f"(d[0]), "+f"(d[1]), "+f"(d[2]), "+f"(d[3])
                 : "r"(a[0]), "r"(a[1]), "r"(a[2]), "r"(a[3]), "r"(b0), "r"(b1));
}
// f16 inputs, f16 accumulator (QK: S comes back packed f16x2, 2 regs)
__device__ __forceinline__ void mma_f16acc(uint32_t* d, const uint32_t* a, uint32_t b0, uint32_t b1) {
    asm volatile("mma.sync.aligned.m16n8k16.row.col.f16.f16.f16.f16 "
                 "{%0,%1},{%2,%3,%4,%5},{%6,%7},{%0,%1};"
                 : "+r"(d[0]), "+r"(d[1])
                 : "r"(a[0]), "r"(a[1]), "r"(a[2]), "r"(a[3]), "r"(b0), "r"(b1));
}
__device__ __forceinline__ void cp16(void* s, const void* g) {
    asm volatile("cp.async.cg.shared.global [%0],[%1],16;" :: "r"(smem_u32(s)), "l"(g));
}
__device__ __forceinline__ void cp_commit() { asm volatile("cp.async.commit_group;"); }
__device__ __forceinline__ void cp_wait0()  { asm volatile("cp.async.wait_group 0;"); }
__device__ __forceinline__ void cp_wait1()  { asm volatile("cp.async.wait_group 1;"); }

// ---------------------------------------------------------------------------
// Prep 1: x -> f16 (scaled by inv_layer).
// ---------------------------------------------------------------------------
__global__ __launch_bounds__(256) void prep_x(const float* __restrict__ x)
{
    size_t e = ((size_t)blockIdx.x * 256 + threadIdx.x) * 8;
    float4 a = *(const float4*)(x + e);
    float4 b = *(const float4*)(x + e + 4);
    uint4 o;
    o.x = pack_f16(a.x * INVL, a.y * INVL);
    o.y = pack_f16(a.z * INVL, a.w * INVL);
    o.z = pack_f16(b.x * INVL, b.y * INVL);
    o.w = pack_f16(b.z * INVL, b.w * INVL);
    *(uint4*)&g_xb[e] = o;
}

// ---------------------------------------------------------------------------
// Prep 2: Wq/Wk/Wv -> g_wb, W0 -> g_w0b.
// ---------------------------------------------------------------------------
__global__ __launch_bounds__(256) void prep_w(
    const float* __restrict__ Wq, const float* __restrict__ Wk,
    const float* __restrict__ Wv, const float* __restrict__ W0)
{
    int idx = blockIdx.x * 256 + threadIdx.x;
    const float* src;
    __half* dst;
    size_t e;
    if (idx < 24576) {
        e = (size_t)idx * 8;
        int r = (int)(e >> 7), c = (int)(e & 127);
        src = (r < HD_) ? Wq + (size_t)r * C_ + c
            : (r < 2 * HD_) ? Wk + (size_t)(r - HD_) * C_ + c
            : Wv + (size_t)(r - 2 * HD_) * C_ + c;
        dst = g_wb + e;
    } else {
        e = (size_t)(idx - 24576) * 8;
        src = W0 + e;
        dst = g_w0b + e;
    }
    float4 a = *(const float4*)src;
    float4 b = *(const float4*)(src + 4);
    uint4 o;
    o.x = pack_f16(a.x, a.y);
    o.y = pack_f16(a.z, a.w);
    o.z = pack_f16(b.x, b.y);
    o.w = pack_f16(b.z, b.w);
    *(uint4*)dst = o;
}

// ---------------------------------------------------------------------------
// Kernel A: QKV (R7 structure, f16).
// ---------------------------------------------------------------------------
__global__ __launch_bounds__(256, 2) void qkv_kernel()
{
    extern __shared__ __align__(16) char smq[];
    __half* Xs = (__half*)smq;        // 2 x [64][136]
    __half* Ws = Xs + 2 * 64 * 136;   // 2 x [128][72]

    int tid = threadIdx.x, lane = tid & 31, w = tid >> 5;
    int g = lane >> 2, tg = lane & 3;
    int mw = w & 3, nw = w >> 2;
    int n0 = blockIdx.x * 128, r0 = blockIdx.y * 128, b = blockIdx.z;

    const __half* xb = g_xb + (size_t)b * C_ * N_;
    const __half* wb = g_wb + (size_t)r0 * C_;

    #pragma unroll
    for (int kc = 0; kc < 2; kc++) {
        #pragma unroll
        for (int t = 0; t < 4; t++) {
            int e = tid + t * 256;
            int c = e >> 4, seg = e & 15;
            cp16(&Xs[kc * 64 * 136 + c * 136 + seg * 8],
                 xb + (size_t)(kc * 64 + c) * N_ + n0 + seg * 8);
        }
        #pragma unroll
        for (int t = 0; t < 4; t++) {
            int e = tid + t * 256;
            int r = e >> 3, seg = e & 7;
            cp16(&Ws[kc * 128 * 72 + r * 72 + seg * 8],
                 wb + (size_t)r * C_ + kc * 64 + seg * 8);
        }
        cp_commit();
    }

    float acc[2][8][4];
    #pragma unroll
    for (int i = 0; i < 2; i++)
        #pragma unroll
        for (int j = 0; j < 8; j++)
            #pragma unroll
            for (int k = 0; k < 4; k++) acc[i][j][k] = 0.0f;

    #pragma unroll
    for (int kc = 0; kc < 2; kc++) {
        if (kc == 0) cp_wait1(); else cp_wait0();
        __syncthreads();
        const __half* Xc = Xs + kc * 64 * 136;
        const __half* Wc = Ws + kc * 128 * 72;

        #pragma unroll
        for (int ks = 0; ks < 64; ks += 16) {
            uint32_t a[2][4];
            #pragma unroll
            for (int mt = 0; mt < 2; mt++) {
                int row = ks + (lane & 7) + ((lane >> 4) << 3);
                int col = mw * 32 + mt * 16 + ((lane >> 3) & 1) * 8;
                ldsm4t(a[mt][0], a[mt][1], a[mt][2], a[mt][3], smem_u32(&Xc[row * 136 + col]));
            }
            #pragma unroll
            for (int ntp = 0; ntp < 4; ntp++) {
                uint32_t b0, b1, b2, b3;
                int row = nw * 64 + ntp * 16 + (lane & 7) + ((lane >> 4) << 3);
                int col = ks + ((lane >> 3) & 1) * 8;
                ldsm4(b0, b1, b2, b3, smem_u32(&Wc[row * 72 + col]));
                #pragma unroll
                for (int mt = 0; mt < 2; mt++) {
                    mma_f32acc(acc[mt][2 * ntp],     a[mt], b0, b1);
                    mma_f32acc(acc[mt][2 * ntp + 1], a[mt], b2, b3);
                }
            }
        }
    }

    float qs = (r0 < HD_) ? QSC : 1.0f;
    __half* ob = g_qkv + (size_t)b * N_ * R3_;
    #pragma unroll
    for (int mt = 0; mt < 2; mt++) {
        int na = n0 + mw * 32 + mt * 16 + g;
        #pragma unroll
        for (int nt = 0; nt < 8; nt++) {
            int rc = r0 + nw * 64 + nt * 8 + 2 * tg;
            *(uint32_t*)&ob[(size_t)na * R3_ + rc] =
                pack_f16(acc[mt][nt][0] * qs, acc[mt][nt][1] * qs);
            *(uint32_t*)&ob[(size_t)(na + 8) * R3_ + rc] =
                pack_f16(acc[mt][nt][2] * qs, acc[mt][nt][3] * qs);
        }
    }
}

// ---------------------------------------------------------------------------
// Kernel B: flash attention, fp16. QK uses f16 ACCUMULATORS: S arrives packed
// f16x2 (2 regs per jt), bias pre-loaded into the C fragment, exp applied
// directly on the packed regs -> PV A-fragments. l via ones-mma (f32 acc).
// ---------------------------------------------------------------------------
__global__ __launch_bounds__(128, 2) void attn_kernel(const float* __restrict__ R)
{
    extern __shared__ __align__(16) char smraw[];
    __half* Qs = (__half*)smraw;                 // [128][72]
    __half* Kb = Qs + 128 * 72;                  // 3 x [64][72]
    __half* Vb = Kb + 3 * 64 * 72;               // 3 x [64][72]
    uint32_t* Rp = (uint32_t*)(Vb + 3 * 64 * 72);  // [32][32] f16x2 pairs (c, c-1)

    int tid = threadIdx.x, lane = tid & 31, w = tid >> 5;
    int g = lane >> 2, tg = lane & 3;
    int i0 = blockIdx.x * 128, h = blockIdx.y, b = blockIdx.z;
    int m0 = w * 32;

    const __half* qb = g_qkv + (size_t)b * N_ * R3_;
    const __half* Qg = qb + h * DK_;
    const __half* Kg = qb + HD_ + h * DK_;
    const __half* Vg = qb + 2 * HD_ + h * DK_;

    #pragma unroll
    for (int t = 0; t < 8; t++) {
        int e = tid + t * 128;
        int i = e >> 3, seg = e & 7;
        cp16(&Qs[i * 72 + seg * 8], Qg + (size_t)(i0 + i) * R3_ + seg * 8);
    }
    #pragma unroll
    for (int t = 0; t < 4; t++) {
        int e = tid + t * 128;
        int j = e >> 3, seg = e & 7;
        cp16(&Kb[j * 72 + seg * 8], Kg + (size_t)j * R3_ + seg * 8);
        cp16(&Vb[j * 72 + seg * 8], Vg + (size_t)j * R3_ + seg * 8);
    }
    cp_commit();
    #pragma unroll
    for (int t = 0; t < 4; t++) {
        int e = tid + t * 128;
        int j = e >> 3, seg = e & 7;
        cp16(&Kb[64 * 72 + j * 72 + seg * 8], Kg + (size_t)(64 + j) * R3_ + seg * 8);
        cp16(&Vb[64 * 72 + j * 72 + seg * 8], Vg + (size_t)(64 + j) * R3_ + seg * 8);
    }
    cp_commit();
    // bias table as f16x2 (c, c-1) pairs, scaled by QSC
    #pragma unroll
    for (int t = 0; t < 8; t++) {
        int idx = tid + t * 128;
        int r = idx >> 5, c = idx & 31;
        const float* Rr = R + h * 1024 + r * 32;
        Rp[idx] = pack_f16(Rr[c] * QSC, Rr[(c - 1) & 31] * QSC);
    }

    float o[2][8][4];
    #pragma unroll
    for (int mh = 0; mh < 2; mh++)
        #pragma unroll
        for (int dt = 0; dt < 8; dt++)
            #pragma unroll
            for (int r = 0; r < 4; r++) o[mh][dt][r] = 0.0f;
    float lacc[2][4] = {{0, 0, 0, 0}, {0, 0, 0, 0}};

    int iA[2], iB[2], i1a[2], i1b[2], dA[2], dB[2];
    #pragma unroll
    for (int mh = 0; mh < 2; mh++) {
        iA[mh] = i0 + m0 + mh * 16 + g;
        iB[mh] = iA[mh] + 8;
        i1a[mh] = iA[mh] >> 5;
        i1b[mh] = iB[mh] >> 5;
        dA[mh] = (iA[mh] & 31) - 2 * tg;
        dB[mh] = (iB[mh] & 31) - 2 * tg;
    }

    cp_wait1();
    __syncthreads();
    uint32_t qf[2][4][4];
    #pragma unroll
    for (int mh = 0; mh < 2; mh++)
        #pragma unroll
        for (int ks4 = 0; ks4 < 4; ks4++)
            ldsm4(qf[mh][ks4][0], qf[mh][ks4][1], qf[mh][ks4][2], qf[mh][ks4][3],
                  smem_u32(&Qs[(m0 + mh * 16 + (lane & 15)) * 72 + ks4 * 16 + (lane >> 4) * 8]));

    for (int it = 0; it < 16; it++) {
        if (it == 15) cp_wait0(); else cp_wait1();
        __syncthreads();
        if (it < 14) {
            int st = (it + 2) % 3;
            int j0n = (it + 2) * 64;
            #pragma unroll
            for (int t = 0; t < 4; t++) {
                int e = tid + t * 128;
                int j = e >> 3, seg = e & 7;
                cp16(&Kb[st * 64 * 72 + j * 72 + seg * 8], Kg + (size_t)(j0n + j) * R3_ + seg * 8);
                cp16(&Vb[st * 64 * 72 + j * 72 + seg * 8], Vg + (size_t)(j0n + j) * R3_ + seg * 8);
            }
            cp_commit();
        }
        int cur = it % 3;
        const __half* Ks = Kb + cur * 64 * 72;
        const __half* Vs = Vb + cur * 64 * 72;

        // ---- init packed-f16 S accumulators from bias pairs ----
        uint32_t s2[2][8][2];   // [mh][jt][rowA pair, rowB pair]
        #pragma unroll
        for (int mh = 0; mh < 2; mh++) {
            const uint32_t* RA0 = Rp + (((i1a[mh] - 2 * it)     & 31) << 5);
            const uint32_t* RA1 = Rp + (((i1a[mh] - 2 * it - 1) & 31) << 5);
            const uint32_t* RB0 = Rp + (((i1b[mh] - 2 * it)     & 31) << 5);
            const uint32_t* RB1 = Rp + (((i1b[mh] - 2 * it - 1) & 31) << 5);
            #pragma unroll
            for (int jt = 0; jt < 8; jt++) {
                const uint32_t* ra = (jt < 4) ? RA0 : RA1;
                const uint32_t* rb = (jt < 4) ? RB0 : RB1;
                int k8 = (jt & 3) * 8;
                s2[mh][jt][0] = ra[(dA[mh] - k8) & 31];
                s2[mh][jt][1] = rb[(dB[mh] - k8) & 31];
            }
        }

        // ---- S += Q K^T (f16 accumulate) ----
        #pragma unroll
        for (int ks4 = 0; ks4 < 4; ks4++) {
            #pragma unroll
            for (int ntp = 0; ntp < 4; ntp++) {
                uint32_t b0, b1, b2, b3;
                int row = ntp * 16 + (lane & 7) + ((lane >> 4) << 3);
                int col = ks4 * 16 + ((lane >> 3) & 1) * 8;
                ldsm4(b0, b1, b2, b3, smem_u32(&Ks[row * 72 + col]));
                #pragma unroll
                for (int mh = 0; mh < 2; mh++) {
                    mma_f16acc(s2[mh][2 * ntp],     qf[mh][ks4], b0, b1);
                    mma_f16acc(s2[mh][2 * ntp + 1], qf[mh][ks4], b2, b3);
                }
            }
        }

        // ---- exp directly on packed regs; l via ones-mma; O += P V ----
        #pragma unroll
        for (int kq = 0; kq < 4; kq++) {
            uint32_t a2[2][4];
            #pragma unroll
            for (int mh = 0; mh < 2; mh++) {
                a2[mh][0] = ex2_f16x2(s2[mh][2 * kq][0]);
                a2[mh][1] = ex2_f16x2(s2[mh][2 * kq][1]);
                a2[mh][2] = ex2_f16x2(s2[mh][2 * kq + 1][0]);
                a2[mh][3] = ex2_f16x2(s2[mh][2 * kq + 1][1]);
                mma_f32acc(lacc[mh], a2[mh], ONESH, ONESH);
            }
            #pragma unroll
            for (int dtp = 0; dtp < 4; dtp++) {
                uint32_t b0, b1, b2, b3;
                int row = kq * 16 + (lane & 7) + ((lane >> 3) & 1) * 8;
                int col = (2 * dtp + (lane >> 4)) * 8;
                ldsm4t(b0, b1, b2, b3, smem_u32(&Vs[row * 72 + col]));
                #pragma unroll
                for (int mh = 0; mh < 2; mh++) {
                    mma_f32acc(o[mh][2 * dtp],     a2[mh], b0, b1);
                    mma_f32acc(o[mh][2 * dtp + 1], a2[mh], b2, b3);
                }
            }
        }
    }

    __half* ab = g_att + (size_t)b * N_ * HD_;
    #pragma unroll
    for (int mh = 0; mh < 2; mh++) {
        float invA = 1.0f / lacc[mh][0], invB = 1.0f / lacc[mh][2];
        #pragma unroll
        for (int dt = 0; dt < 8; dt++) {
            int col = h * DK_ + dt * 8 + 2 * tg;
            *(uint32_t*)&ab[(size_t)iA[mh] * HD_ + col] =
                pack_f16(o[mh][dt][0] * invA, o[mh][dt][1] * invA);
            *(uint32_t*)&ab[(size_t)iB[mh] * HD_ + col] =
                pack_f16(o[mh][dt][2] * invB, o[mh][dt][3] * invB);
        }
    }
}

// ---------------------------------------------------------------------------
// Kernel C: out[b][c][n] = W0[c] . att[b][n] + x[b][c][n]  (R7 structure, f16)
// ---------------------------------------------------------------------------
__global__ __launch_bounds__(256, 2) void out_kernel(
    const float* __restrict__ x,
    float* __restrict__ out)
{
    extern __shared__ __align__(16) char smo[];
    __half* W0s = (__half*)smo;       // 2 x [128][72]
    __half* As  = W0s + 2 * 128 * 72; // 2 x [128][72]

    int tid = threadIdx.x, lane = tid & 31, w = tid >> 5;
    int g = lane >> 2, tg = lane & 3;
    int mw = w & 3, nw = w >> 2;
    int n0 = blockIdx.x * 128, b = blockIdx.y;

    const __half* ab = g_att + (size_t)b * N_ * HD_;

    #pragma unroll
    for (int t = 0; t < 4; t++) {
        int e = tid + t * 256;
        int r = e >> 3, seg = e & 7;
        cp16(&W0s[r * 72 + seg * 8], g_w0b + (size_t)r * HD_ + seg * 8);
        cp16(&As[r * 72 + seg * 8],  ab + (size_t)(n0 + r) * HD_ + seg * 8);
    }
    cp_commit();

    float acc[2][8][4];
    #pragma unroll
    for (int i = 0; i < 2; i++)
        #pragma unroll
        for (int j = 0; j < 8; j++)
            #pragma unroll
            for (int k = 0; k < 4; k++) acc[i][j][k] = 0.0f;

    for (int kc = 0; kc < 8; kc++) {
        cp_wait0();
        __syncthreads();
        int cur = kc & 1;
        if (kc < 7) {
            int nb = cur ^ 1;
            int k0n = (kc + 1) * 64;
            #pragma unroll
            for (int t = 0; t < 4; t++) {
                int e = tid + t * 256;
                int r = e >> 3, seg = e & 7;
                cp16(&W0s[nb * 128 * 72 + r * 72 + seg * 8],
                     g_w0b + (size_t)r * HD_ + k0n + seg * 8);
                cp16(&As[nb * 128 * 72 + r * 72 + seg * 8],
                     ab + (size_t)(n0 + r) * HD_ + k0n + seg * 8);
            }
            cp_commit();
        }
        const __half* Wc = W0s + cur * 128 * 72;
        const __half* Ac = As  + cur * 128 * 72;

        #pragma unroll
        for (int ks = 0; ks < 64; ks += 16) {
            uint32_t a[2][4];
            #pragma unroll
            for (int mt = 0; mt < 2; mt++) {
                int row = mw * 32 + mt * 16 + (lane & 15);
                int col = ks + (lane >> 4) * 8;
                ldsm4(a[mt][0], a[mt][1], a[mt][2], a[mt][3], smem_u32(&Wc[row * 72 + col]));
            }
            #pragma unroll
            for (int ntp = 0; ntp < 4; ntp++) {
                uint32_t b0, b1, b2, b3;
                int row = nw * 64 + ntp * 16 + (lane & 7) + ((lane >> 4) << 3);
                int col = ks + ((lane >> 3) & 1) * 8;
                ldsm4(b0, b1, b2, b3, smem_u32(&Ac[row * 72 + col]));
                #pragma unroll
                for (int mt = 0; mt < 2; mt++) {
                    mma_f32acc(acc[mt][2 * ntp],     a[mt], b0, b1);
                    mma_f32acc(acc[mt][2 * ntp + 1], a[mt], b2, b3);
                }
            }
        }
    }

    const float* xb = x + (size_t)b * C_ * N_;
    float* ob = out + (size_t)b * C_ * N_;
    #pragma unroll
    for (int mt = 0; mt < 2; mt++) {
        int row_a = mw * 32 + mt * 16 + g;
        #pragma unroll
        for (int nt = 0; nt < 8; nt++) {
            int col = n0 + nw * 64 + nt * 8 + 2 * tg;
            float2 xa = *(const float2*)&xb[(size_t)row_a * N_ + col];
            float2 va = make_float2(acc[mt][nt][0] + xa.x, acc[mt][nt][1] + xa.y);
            *(float2*)&ob[(size_t)row_a * N_ + col] = va;
            float2 xbv = *(const float2*)&xb[(size_t)(row_a + 8) * N_ + col];
            float2 vb = make_float2(acc[mt][nt][2] + xbv.x, acc[mt][nt][3] + xbv.y);
            *(float2*)&ob[(size_t)(row_a + 8) * N_ + col] = vb;
        }
    }
}

// ---------------------------------------------------------------------------
extern "C" void kernel_launch(void* const* d_in, const int* in_sizes, int n_in,
                              void* d_out, int out_size)
{
    const float* x  = (const float*)d_in[0];
    const float* Wq = (const float*)d_in[1];
    const float* Wk = (const float*)d_in[2];
    const float* Wv = (const float*)d_in[3];
    const float* R  = (const float*)d_in[4];
    const float* W0 = (const float*)d_in[5];
    float* out = (float*)d_out;

    const int QKV_SMEM  = (2 * 64 * 136 + 2 * 128 * 72) * 2;            // 71680 B
    const int ATTN_SMEM = (128 * 72 + 6 * 64 * 72) * 2 + 32 * 32 * 4;   // 77824 B
    const int OUT_SMEM  = (4 * 128 * 72) * 2;                           // 73728 B
    cudaFuncSetAttribute(qkv_kernel,  cudaFuncAttributeMaxDynamicSharedMemorySize, QKV_SMEM);
    cudaFuncSetAttribute(attn_kernel, cudaFuncAttributeMaxDynamicSharedMemorySize, ATTN_SMEM);
    cudaFuncSetAttribute(out_kernel,  cudaFuncAttributeMaxDynamicSharedMemorySize, OUT_SMEM);

    prep_x<<<2048, 256>>>(x);
    prep_w<<<128, 256>>>(Wq, Wk, Wv, W0);
    qkv_kernel<<<dim3(8, 12, 32), 256, QKV_SMEM>>>();
    attn_kernel<<<dim3(8, 8, 32), 128, ATTN_SMEM>>>(R);
    out_kernel<<<dim3(8, 32), 256, OUT_SMEM>>>(x, out);
}

// round 17
// speedup vs baseline: 1.0059x; 1.0059x over previous
#include <cuda_runtime.h>
#include <cuda_fp16.h>
#include <cstdint>

#define B_   32
#define C_   128
#define N_   1024   // L*L
#define H_   8
#define DK_  64
#define HD_  512    // H*DK
#define R3_  1536   // 3*HD
#define FULL 0xffffffffu

#define QSC  0.1803368801111354f    // 0.125 * log2(e)
#define INVL 0.44721359549995793f   // 1/sqrt(5)
#define ONESH 0x3C003C00u           // f16x2 (1.0, 1.0)

// Scratch (allocation-free contract: __device__ globals), fp16
__device__ __half g_xb [(size_t)B_ * C_ * N_];
__device__ __half g_wb [(size_t)R3_ * C_];
__device__ __half g_w0b[(size_t)C_ * HD_];
__device__ __half g_qkv[(size_t)B_ * N_ * R3_];  // [b][n][r]; Q pre-scaled by QSC
__device__ __half g_att[(size_t)B_ * N_ * HD_];

__device__ __forceinline__ uint32_t smem_u32(const void* p) {
    return (uint32_t)__cvta_generic_to_shared(p);
}
// pack two f32 into f16x2: lo -> bits[15:0], hi -> bits[31:16]
__device__ __forceinline__ uint32_t pack_f16(float lo, float hi) {
    uint32_t r;
    asm("cvt.rn.f16x2.f32 %0, %1, %2;" : "=r"(r) : "f"(hi), "f"(lo));
    return r;
}
__device__ __forceinline__ uint32_t ex2_f16x2(uint32_t x) {
    uint32_t y;
    asm("ex2.approx.f16x2 %0, %1;" : "=r"(y) : "r"(x));
    return y;
}
__device__ __forceinline__ void ldsm4(uint32_t& r0, uint32_t& r1, uint32_t& r2, uint32_t& r3, uint32_t a) {
    asm volatile("ldmatrix.sync.aligned.m8n8.x4.shared.b16 {%0,%1,%2,%3},[%4];"
                 : "=r"(r0), "=r"(r1), "=r"(r2), "=r"(r3) : "r"(a));
}
__device__ __forceinline__ void ldsm4t(uint32_t& r0, uint32_t& r1, uint32_t& r2, uint32_t& r3, uint32_t a) {
    asm volatile("ldmatrix.sync.aligned.m8n8.x4.trans.shared.b16 {%0,%1,%2,%3},[%4];"
                 : "=r"(r0), "=r"(r1), "=r"(r2), "=r"(r3) : "r"(a));
}
// f16 inputs, f32 accumulator (PV, l, qkv, out)
__device__ __forceinline__ void mma_f32acc(float* d, const uint32_t* a, uint32_t b0, uint32_t b1) {
    asm volatile("mma.sync.aligned.m16n8k16.row.col.f32.f16.f16.f32 "
                 "{%0,%1,%2,%3},{%4,%5,%6,%7},{%8,%9},{%0,%1,%2,%3};"
                 : "+f"(d[0]), "+f"(d[1]), "+f"(d[2]), "+f"(d[3])
                 : "r"(a[0]), "r"(a[1]), "r"(a[2]), "r"(a[3]), "r"(b0), "r"(b1));
}
// f16 inputs, f16 accumulator (QK: S comes back packed f16x2, 2 regs)
__device__ __forceinline__ void mma_f16acc(uint32_t* d, const uint32_t* a, uint32_t b0, uint32_t b1) {
    asm volatile("mma.sync.aligned.m16n8k16.row.col.f16.f16.f16.f16 "
                 "{%0,%1},{%2,%3,%4,%5},{%6,%7},{%0,%1};"
                 : "+r"(d[0]), "+r"(d[1])
                 : "r"(a[0]), "r"(a[1]), "r"(a[2]), "r"(a[3]), "r"(b0), "r"(b1));
}
__device__ __forceinline__ void cp16(void* s, const void* g) {
    asm volatile("cp.async.cg.shared.global [%0],[%1],16;" :: "r"(smem_u32(s)), "l"(g));
}
__device__ __forceinline__ void cp_commit() { asm volatile("cp.async.commit_group;"); }
__device__ __forceinline__ void cp_wait0()  { asm volatile("cp.async.wait_group 0;"); }
__device__ __forceinline__ void cp_wait1()  { asm volatile("cp.async.wait_group 1;"); }

// ---------------------------------------------------------------------------
// Prep 1: x -> f16 (scaled by inv_layer).
// ---------------------------------------------------------------------------
__global__ __launch_bounds__(256) void prep_x(const float* __restrict__ x)
{
    size_t e = ((size_t)blockIdx.x * 256 + threadIdx.x) * 8;
    float4 a = *(const float4*)(x + e);
    float4 b = *(const float4*)(x + e + 4);
    uint4 o;
    o.x = pack_f16(a.x * INVL, a.y * INVL);
    o.y = pack_f16(a.z * INVL, a.w * INVL);
    o.z = pack_f16(b.x * INVL, b.y * INVL);
    o.w = pack_f16(b.z * INVL, b.w * INVL);
    *(uint4*)&g_xb[e] = o;
}

// ---------------------------------------------------------------------------
// Prep 2: Wq/Wk/Wv -> g_wb, W0 -> g_w0b.
// ---------------------------------------------------------------------------
__global__ __launch_bounds__(256) void prep_w(
    const float* __restrict__ Wq, const float* __restrict__ Wk,
    const float* __restrict__ Wv, const float* __restrict__ W0)
{
    int idx = blockIdx.x * 256 + threadIdx.x;
    const float* src;
    __half* dst;
    size_t e;
    if (idx < 24576) {
        e = (size_t)idx * 8;
        int r = (int)(e >> 7), c = (int)(e & 127);
        src = (r < HD_) ? Wq + (size_t)r * C_ + c
            : (r < 2 * HD_) ? Wk + (size_t)(r - HD_) * C_ + c
            : Wv + (size_t)(r - 2 * HD_) * C_ + c;
        dst = g_wb + e;
    } else {
        e = (size_t)(idx - 24576) * 8;
        src = W0 + e;
        dst = g_w0b + e;
    }
    float4 a = *(const float4*)src;
    float4 b = *(const float4*)(src + 4);
    uint4 o;
    o.x = pack_f16(a.x, a.y);
    o.y = pack_f16(a.z, a.w);
    o.z = pack_f16(b.x, b.y);
    o.w = pack_f16(b.z, b.w);
    *(uint4*)dst = o;
}

// ---------------------------------------------------------------------------
// Kernel A: QKV (R7 structure, f16).
// ---------------------------------------------------------------------------
__global__ __launch_bounds__(256, 2) void qkv_kernel()
{
    extern __shared__ __align__(16) char smq[];
    __half* Xs = (__half*)smq;        // 2 x [64][136]
    __half* Ws = Xs + 2 * 64 * 136;   // 2 x [128][72]

    int tid = threadIdx.x, lane = tid & 31, w = tid >> 5;
    int g = lane >> 2, tg = lane & 3;
    int mw = w & 3, nw = w >> 2;
    int n0 = blockIdx.x * 128, r0 = blockIdx.y * 128, b = blockIdx.z;

    const __half* xb = g_xb + (size_t)b * C_ * N_;
    const __half* wb = g_wb + (size_t)r0 * C_;

    #pragma unroll
    for (int kc = 0; kc < 2; kc++) {
        #pragma unroll
        for (int t = 0; t < 4; t++) {
            int e = tid + t * 256;
            int c = e >> 4, seg = e & 15;
            cp16(&Xs[kc * 64 * 136 + c * 136 + seg * 8],
                 xb + (size_t)(kc * 64 + c) * N_ + n0 + seg * 8);
        }
        #pragma unroll
        for (int t = 0; t < 4; t++) {
            int e = tid + t * 256;
            int r = e >> 3, seg = e & 7;
            cp16(&Ws[kc * 128 * 72 + r * 72 + seg * 8],
                 wb + (size_t)r * C_ + kc * 64 + seg * 8);
        }
        cp_commit();
    }

    float acc[2][8][4];
    #pragma unroll
    for (int i = 0; i < 2; i++)
        #pragma unroll
        for (int j = 0; j < 8; j++)
            #pragma unroll
            for (int k = 0; k < 4; k++) acc[i][j][k] = 0.0f;

    #pragma unroll
    for (int kc = 0; kc < 2; kc++) {
        if (kc == 0) cp_wait1(); else cp_wait0();
        __syncthreads();
        const __half* Xc = Xs + kc * 64 * 136;
        const __half* Wc = Ws + kc * 128 * 72;

        #pragma unroll
        for (int ks = 0; ks < 64; ks += 16) {
            uint32_t a[2][4];
            #pragma unroll
            for (int mt = 0; mt < 2; mt++) {
                int row = ks + (lane & 7) + ((lane >> 4) << 3);
                int col = mw * 32 + mt * 16 + ((lane >> 3) & 1) * 8;
                ldsm4t(a[mt][0], a[mt][1], a[mt][2], a[mt][3], smem_u32(&Xc[row * 136 + col]));
            }
            #pragma unroll
            for (int ntp = 0; ntp < 4; ntp++) {
                uint32_t b0, b1, b2, b3;
                int row = nw * 64 + ntp * 16 + (lane & 7) + ((lane >> 4) << 3);
                int col = ks + ((lane >> 3) & 1) * 8;
                ldsm4(b0, b1, b2, b3, smem_u32(&Wc[row * 72 + col]));
                #pragma unroll
                for (int mt = 0; mt < 2; mt++) {
                    mma_f32acc(acc[mt][2 * ntp],     a[mt], b0, b1);
                    mma_f32acc(acc[mt][2 * ntp + 1], a[mt], b2, b3);
                }
            }
        }
    }

    float qs = (r0 < HD_) ? QSC : 1.0f;
    __half* ob = g_qkv + (size_t)b * N_ * R3_;
    #pragma unroll
    for (int mt = 0; mt < 2; mt++) {
        int na = n0 + mw * 32 + mt * 16 + g;
        #pragma unroll
        for (int nt = 0; nt < 8; nt++) {
            int rc = r0 + nw * 64 + nt * 8 + 2 * tg;
            *(uint32_t*)&ob[(size_t)na * R3_ + rc] =
                pack_f16(acc[mt][nt][0] * qs, acc[mt][nt][1] * qs);
            *(uint32_t*)&ob[(size_t)(na + 8) * R3_ + rc] =
                pack_f16(acc[mt][nt][2] * qs, acc[mt][nt][3] * qs);
        }
    }
}

// ---------------------------------------------------------------------------
// Kernel B: flash attention, fp16. QK uses f16 ACCUMULATORS: S arrives packed
// f16x2 (2 regs per jt), bias pre-loaded into the C fragment, exp applied
// directly on the packed regs -> PV A-fragments. l via ones-mma (f32 acc).
// ---------------------------------------------------------------------------
__global__ __launch_bounds__(128, 2) void attn_kernel(const float* __restrict__ R)
{
    extern __shared__ __align__(16) char smraw[];
    __half* Qs = (__half*)smraw;                 // [128][72]
    __half* Kb = Qs + 128 * 72;                  // 3 x [64][72]
    __half* Vb = Kb + 3 * 64 * 72;               // 3 x [64][72]
    uint32_t* Rp = (uint32_t*)(Vb + 3 * 64 * 72);  // [32][32] f16x2 pairs (c, c-1)

    int tid = threadIdx.x, lane = tid & 31, w = tid >> 5;
    int g = lane >> 2, tg = lane & 3;
    int i0 = blockIdx.x * 128, h = blockIdx.y, b = blockIdx.z;
    int m0 = w * 32;

    const __half* qb = g_qkv + (size_t)b * N_ * R3_;
    const __half* Qg = qb + h * DK_;
    const __half* Kg = qb + HD_ + h * DK_;
    const __half* Vg = qb + 2 * HD_ + h * DK_;

    #pragma unroll
    for (int t = 0; t < 8; t++) {
        int e = tid + t * 128;
        int i = e >> 3, seg = e & 7;
        cp16(&Qs[i * 72 + seg * 8], Qg + (size_t)(i0 + i) * R3_ + seg * 8);
    }
    #pragma unroll
    for (int t = 0; t < 4; t++) {
        int e = tid + t * 128;
        int j = e >> 3, seg = e & 7;
        cp16(&Kb[j * 72 + seg * 8], Kg + (size_t)j * R3_ + seg * 8);
        cp16(&Vb[j * 72 + seg * 8], Vg + (size_t)j * R3_ + seg * 8);
    }
    cp_commit();
    #pragma unroll
    for (int t = 0; t < 4; t++) {
        int e = tid + t * 128;
        int j = e >> 3, seg = e & 7;
        cp16(&Kb[64 * 72 + j * 72 + seg * 8], Kg + (size_t)(64 + j) * R3_ + seg * 8);
        cp16(&Vb[64 * 72 + j * 72 + seg * 8], Vg + (size_t)(64 + j) * R3_ + seg * 8);
    }
    cp_commit();
    // bias table as f16x2 (c, c-1) pairs, scaled by QSC
    #pragma unroll
    for (int t = 0; t < 8; t++) {
        int idx = tid + t * 128;
        int r = idx >> 5, c = idx & 31;
        const float* Rr = R + h * 1024 + r * 32;
        Rp[idx] = pack_f16(Rr[c] * QSC, Rr[(c - 1) & 31] * QSC);
    }

    float o[2][8][4];
    #pragma unroll
    for (int mh = 0; mh < 2; mh++)
        #pragma unroll
        for (int dt = 0; dt < 8; dt++)
            #pragma unroll
            for (int r = 0; r < 4; r++) o[mh][dt][r] = 0.0f;
    float lacc[2][4] = {{0, 0, 0, 0}, {0, 0, 0, 0}};

    int iA[2], iB[2], i1a[2], i1b[2], dA[2], dB[2];
    #pragma unroll
    for (int mh = 0; mh < 2; mh++) {
        iA[mh] = i0 + m0 + mh * 16 + g;
        iB[mh] = iA[mh] + 8;
        i1a[mh] = iA[mh] >> 5;
        i1b[mh] = iB[mh] >> 5;
        dA[mh] = (iA[mh] & 31) - 2 * tg;
        dB[mh] = (iB[mh] & 31) - 2 * tg;
    }

    cp_wait1();
    __syncthreads();
    uint32_t qf[2][4][4];
    #pragma unroll
    for (int mh = 0; mh < 2; mh++)
        #pragma unroll
        for (int ks4 = 0; ks4 < 4; ks4++)
            ldsm4(qf[mh][ks4][0], qf[mh][ks4][1], qf[mh][ks4][2], qf[mh][ks4][3],
                  smem_u32(&Qs[(m0 + mh * 16 + (lane & 15)) * 72 + ks4 * 16 + (lane >> 4) * 8]));

    for (int it = 0; it < 16; it++) {
        if (it == 15) cp_wait0(); else cp_wait1();
        __syncthreads();
        if (it < 14) {
            int st = (it + 2) % 3;
            int j0n = (it + 2) * 64;
            #pragma unroll
            for (int t = 0; t < 4; t++) {
                int e = tid + t * 128;
                int j = e >> 3, seg = e & 7;
                cp16(&Kb[st * 64 * 72 + j * 72 + seg * 8], Kg + (size_t)(j0n + j) * R3_ + seg * 8);
                cp16(&Vb[st * 64 * 72 + j * 72 + seg * 8], Vg + (size_t)(j0n + j) * R3_ + seg * 8);
            }
            cp_commit();
        }
        int cur = it % 3;
        const __half* Ks = Kb + cur * 64 * 72;
        const __half* Vs = Vb + cur * 64 * 72;

        // ---- init packed-f16 S accumulators from bias pairs ----
        uint32_t s2[2][8][2];   // [mh][jt][rowA pair, rowB pair]
        #pragma unroll
        for (int mh = 0; mh < 2; mh++) {
            const uint32_t* RA0 = Rp + (((i1a[mh] - 2 * it)     & 31) << 5);
            const uint32_t* RA1 = Rp + (((i1a[mh] - 2 * it - 1) & 31) << 5);
            const uint32_t* RB0 = Rp + (((i1b[mh] - 2 * it)     & 31) << 5);
            const uint32_t* RB1 = Rp + (((i1b[mh] - 2 * it - 1) & 31) << 5);
            #pragma unroll
            for (int jt = 0; jt < 8; jt++) {
                const uint32_t* ra = (jt < 4) ? RA0 : RA1;
                const uint32_t* rb = (jt < 4) ? RB0 : RB1;
                int k8 = (jt & 3) * 8;
                s2[mh][jt][0] = ra[(dA[mh] - k8) & 31];
                s2[mh][jt][1] = rb[(dB[mh] - k8) & 31];
            }
        }

        // ---- S += Q K^T (f16 accumulate) ----
        #pragma unroll
        for (int ks4 = 0; ks4 < 4; ks4++) {
            #pragma unroll
            for (int ntp = 0; ntp < 4; ntp++) {
                uint32_t b0, b1, b2, b3;
                int row = ntp * 16 + (lane & 7) + ((lane >> 4) << 3);
                int col = ks4 * 16 + ((lane >> 3) & 1) * 8;
                ldsm4(b0, b1, b2, b3, smem_u32(&Ks[row * 72 + col]));
                #pragma unroll
                for (int mh = 0; mh < 2; mh++) {
                    mma_f16acc(s2[mh][2 * ntp],     qf[mh][ks4], b0, b1);
                    mma_f16acc(s2[mh][2 * ntp + 1], qf[mh][ks4], b2, b3);
                }
            }
        }

        // ---- exp directly on packed regs; l via ones-mma; O += P V ----
        #pragma unroll
        for (int kq = 0; kq < 4; kq++) {
            uint32_t a2[2][4];
            #pragma unroll
            for (int mh = 0; mh < 2; mh++) {
                a2[mh][0] = ex2_f16x2(s2[mh][2 * kq][0]);
                a2[mh][1] = ex2_f16x2(s2[mh][2 * kq][1]);
                a2[mh][2] = ex2_f16x2(s2[mh][2 * kq + 1][0]);
                a2[mh][3] = ex2_f16x2(s2[mh][2 * kq + 1][1]);
                mma_f32acc(lacc[mh], a2[mh], ONESH, ONESH);
            }
            #pragma unroll
            for (int dtp = 0; dtp < 4; dtp++) {
                uint32_t b0, b1, b2, b3;
                int row = kq * 16 + (lane & 7) + ((lane >> 3) & 1) * 8;
                int col = (2 * dtp + (lane >> 4)) * 8;
                ldsm4t(b0, b1, b2, b3, smem_u32(&Vs[row * 72 + col]));
                #pragma unroll
                for (int mh = 0; mh < 2; mh++) {
                    mma_f32acc(o[mh][2 * dtp],     a2[mh], b0, b1);
                    mma_f32acc(o[mh][2 * dtp + 1], a2[mh], b2, b3);
                }
            }
        }
    }

    __half* ab = g_att + (size_t)b * N_ * HD_;
    #pragma unroll
    for (int mh = 0; mh < 2; mh++) {
        float invA = 1.0f / lacc[mh][0], invB = 1.0f / lacc[mh][2];
        #pragma unroll
        for (int dt = 0; dt < 8; dt++) {
            int col = h * DK_ + dt * 8 + 2 * tg;
            *(uint32_t*)&ab[(size_t)iA[mh] * HD_ + col] =
                pack_f16(o[mh][dt][0] * invA, o[mh][dt][1] * invA);
            *(uint32_t*)&ab[(size_t)iB[mh] * HD_ + col] =
                pack_f16(o[mh][dt][2] * invB, o[mh][dt][3] * invB);
        }
    }
}

// ---------------------------------------------------------------------------
// Kernel C: out[b][c][n] = W0[c] . att[b][n] + x[b][c][n]  (R7 structure, f16)
// ---------------------------------------------------------------------------
__global__ __launch_bounds__(256, 2) void out_kernel(
    const float* __restrict__ x,
    float* __restrict__ out)
{
    extern __shared__ __align__(16) char smo[];
    __half* W0s = (__half*)smo;       // 2 x [128][72]
    __half* As  = W0s + 2 * 128 * 72; // 2 x [128][72]

    int tid = threadIdx.x, lane = tid & 31, w = tid >> 5;
    int g = lane >> 2, tg = lane & 3;
    int mw = w & 3, nw = w >> 2;
    int n0 = blockIdx.x * 128, b = blockIdx.y;

    const __half* ab = g_att + (size_t)b * N_ * HD_;

    #pragma unroll
    for (int t = 0; t < 4; t++) {
        int e = tid + t * 256;
        int r = e >> 3, seg = e & 7;
        cp16(&W0s[r * 72 + seg * 8], g_w0b + (size_t)r * HD_ + seg * 8);
        cp16(&As[r * 72 + seg * 8],  ab + (size_t)(n0 + r) * HD_ + seg * 8);
    }
    cp_commit();

    float acc[2][8][4];
    #pragma unroll
    for (int i = 0; i < 2; i++)
        #pragma unroll
        for (int j = 0; j < 8; j++)
            #pragma unroll
            for (int k = 0; k < 4; k++) acc[i][j][k] = 0.0f;

    for (int kc = 0; kc < 8; kc++) {
        cp_wait0();
        __syncthreads();
        int cur = kc & 1;
        if (kc < 7) {
            int nb = cur ^ 1;
            int k0n = (kc + 1) * 64;
            #pragma unroll
            for (int t = 0; t < 4; t++) {
                int e = tid + t * 256;
                int r = e >> 3, seg = e & 7;
                cp16(&W0s[nb * 128 * 72 + r * 72 + seg * 8],
                     g_w0b + (size_t)r * HD_ + k0n + seg * 8);
                cp16(&As[nb * 128 * 72 + r * 72 + seg * 8],
                     ab + (size_t)(n0 + r) * HD_ + k0n + seg * 8);
            }
            cp_commit();
        }
        const __half* Wc = W0s + cur * 128 * 72;
        const __half* Ac = As  + cur * 128 * 72;

        #pragma unroll
        for (int ks = 0; ks < 64; ks += 16) {
            uint32_t a[2][4];
            #pragma unroll
            for (int mt = 0; mt < 2; mt++) {
                int row = mw * 32 + mt * 16 + (lane & 15);
                int col = ks + (lane >> 4) * 8;
                ldsm4(a[mt][0], a[mt][1], a[mt][2], a[mt][3], smem_u32(&Wc[row * 72 + col]));
            }
            #pragma unroll
            for (int ntp = 0; ntp < 4; ntp++) {
                uint32_t b0, b1, b2, b3;
                int row = nw * 64 + ntp * 16 + (lane & 7) + ((lane >> 4) << 3);
                int col = ks + ((lane >> 3) & 1) * 8;
                ldsm4(b0, b1, b2, b3, smem_u32(&Ac[row * 72 + col]));
                #pragma unroll
                for (int mt = 0; mt < 2; mt++) {
                    mma_f32acc(acc[mt][2 * ntp],     a[mt], b0, b1);
                    mma_f32acc(acc[mt][2 * ntp + 1], a[mt], b2, b3);
                }
            }
        }
    }

    const float* xb = x + (size_t)b * C_ * N_;
    float* ob = out + (size_t)b * C_ * N_;
    #pragma unroll
    for (int mt = 0; mt < 2; mt++) {
        int row_a = mw * 32 + mt * 16 + g;
        #pragma unroll
        for (int nt = 0; nt < 8; nt++) {
            int col = n0 + nw * 64 + nt * 8 + 2 * tg;
            float2 xa = *(const float2*)&xb[(size_t)row_a * N_ + col];
            float2 va = make_float2(acc[mt][nt][0] + xa.x, acc[mt][nt][1] + xa.y);
            *(float2*)&ob[(size_t)row_a * N_ + col] = va;
            float2 xbv = *(const float2*)&xb[(size_t)(row_a + 8) * N_ + col];
            float2 vb = make_float2(acc[mt][nt][2] + xbv.x, acc[mt][nt][3] + xbv.y);
            *(float2*)&ob[(size_t)(row_a + 8) * N_ + col] = vb;
        }
    }
}

// ---------------------------------------------------------------------------
extern "C" void kernel_launch(void* const* d_in, const int* in_sizes, int n_in,
                              void* d_out, int out_size)
{
    const float* x  = (const float*)d_in[0];
    const float* Wq = (const float*)d_in[1];
    const float* Wk = (const float*)d_in[2];
    const float* Wv = (const float*)d_in[3];
    const float* R  = (const float*)d_in[4];
    const float* W0 = (const float*)d_in[5];
    float* out = (float*)d_out;

    const int QKV_SMEM  = (2 * 64 * 136 + 2 * 128 * 72) * 2;            // 71680 B
    const int ATTN_SMEM = (128 * 72 + 6 * 64 * 72) * 2 + 32 * 32 * 4;   // 77824 B
    const int OUT_SMEM  = (4 * 128 * 72) * 2;                           // 73728 B
    cudaFuncSetAttribute(qkv_kernel,  cudaFuncAttributeMaxDynamicSharedMemorySize, QKV_SMEM);
    cudaFuncSetAttribute(attn_kernel, cudaFuncAttributeMaxDynamicSharedMemorySize, ATTN_SMEM);
    cudaFuncSetAttribute(out_kernel,  cudaFuncAttributeMaxDynamicSharedMemorySize, OUT_SMEM);

    prep_x<<<2048, 256>>>(x);
    prep_w<<<128, 256>>>(Wq, Wk, Wv, W0);
    qkv_kernel<<<dim3(8, 12, 32), 256, QKV_SMEM>>>();
    attn_kernel<<<dim3(8, 8, 32), 128, ATTN_SMEM>>>(R);
    out_kernel<<<dim3(8, 32), 256, OUT_SMEM>>>(x, out);
}